// round 6
// baseline (speedup 1.0000x reference)
#include <cuda_runtime.h>
#include <math.h>

// LinearAttention: out = tril(rope(Q) @ rope(K)^T) @ V
//   pass0: trig table  g_trig[t][j] = (cos, sin)(t * invf_j)
//   pass1: per-chunk KV state  S_c = Kr_c^T @ V_c        (streamed 32-row blocks)
//   pass2: exclusive prefix    M_c = sum_{j<c} S_j
//   pass3: out = masked(Qr Kr^T) V + Qr @ M_c            (64-row Q tiles)
// R4: occupancy fix — both heavy kernels fit 2 CTAs/SM (regs<=128, smem cut).
// R5: RoPE fused into gmem->smem load (one less barrier per tile, no smem RMW).

#define BB 8
#define SS 4096
#define DD 128
#define CC 128
#define NC 32          // SS / CC
#define QSTR 132       // padded smem row stride (floats)
#define ESTR 36        // E-tile smem stride

__device__ float4 g_kv4 [(size_t)BB * NC * DD * DD / 4];
__device__ float4 g_pre4[(size_t)BB * NC * DD * DD / 4];
__device__ float2 g_trig[(size_t)SS * 64];            // 2 MB (cos,sin) per (t,j)

union U2 { unsigned long long u; float2 f; };

__device__ __forceinline__ void ffma2(unsigned long long &d,
                                      unsigned long long a,
                                      unsigned long long b) {
    asm("fma.rn.f32x2 %0, %1, %2, %0;" : "+l"(d) : "l"(a), "l"(b));
}
__device__ __forceinline__ unsigned long long bcast2(float x) {
    U2 u; u.f = make_float2(x, x); return u.u;
}

// Plain copy: nrows*128 floats (row-major) -> smem with stride QSTR.
__device__ __forceinline__ void load_tile(float* sdst, const float* __restrict__ gsrc,
                                          int nrows, int tid) {
    int total = nrows * 32;                       // float4 count
    for (int g = tid; g < total; g += 256) {
        int row = g >> 5, c4 = g & 31;
        *(float4*)(sdst + row * QSTR + c4 * 4) = ((const float4*)gsrc)[g];
    }
}

// Fused load+RoPE: rotate (j, j+64) pairs in registers on the way to smem.
__device__ __forceinline__ void load_rope_tile(float* sdst, const float* __restrict__ gsrc,
                                               int nrows, int srow0, int tid) {
    int total = nrows * 16;                       // pair-of-float4 count
    for (int g = tid; g < total; g += 256) {
        int row = g >> 4, c4 = g & 15;
        float4 a = ((const float4*)gsrc)[row * 32 + c4];        // cols 4c4..4c4+3
        float4 b = ((const float4*)gsrc)[row * 32 + c4 + 16];   // cols +64
        const float4* tp = (const float4*)(g_trig + (size_t)(srow0 + row) * 64 + c4 * 4);
        float4 t0 = tp[0], t1 = tp[1];            // (cos,sin) x4, 16B-aligned
        float4 lo, hi;
        lo.x = a.x * t0.x - b.x * t0.y;  hi.x = b.x * t0.x + a.x * t0.y;
        lo.y = a.y * t0.z - b.y * t0.w;  hi.y = b.y * t0.z + a.y * t0.w;
        lo.z = a.z * t1.x - b.z * t1.y;  hi.z = b.z * t1.x + a.z * t1.y;
        lo.w = a.w * t1.z - b.w * t1.w;  hi.w = b.w * t1.z + a.w * t1.w;
        *(float4*)(sdst + row * QSTR + c4 * 4)      = lo;
        *(float4*)(sdst + row * QSTR + c4 * 4 + 64) = hi;
    }
}

// Accurate sincos for |ang| <= ~4100 rad, robust under --use_fast_math.
__device__ __forceinline__ void sincos_safe(float ang, float* sn, float* cs) {
    float k = rintf(ang * 0.15915494309189535f);
    float r = fmaf(-k, 6.28125f, ang);               // exact (8-bit mantissa hi part)
    r = fmaf(-k, 1.9353071795864769e-3f, r);
    sincosf(r, sn, cs);
}

// acc[8][2]: 8 rows x 4 cols. acc[i0+r][d0..d0+3] += sum_e A[i][e]*B[e][d].
__device__ __forceinline__ void gemmC4(const float* __restrict__ A, int astr,
                                       const float* __restrict__ Bm, int bstr,
                                       int red, int i0, int d0,
                                       unsigned long long acc[8][2]) {
    #pragma unroll 2
    for (int e = 0; e < red; e += 4) {
        ulonglong2 b[4];
        #pragma unroll
        for (int k = 0; k < 4; k++)
            b[k] = *(const ulonglong2*)(Bm + (e + k) * bstr + d0);
        #pragma unroll
        for (int r = 0; r < 8; r++) {
            float4 a4 = *(const float4*)(A + (i0 + r) * astr + e);
            unsigned long long a;
            a = bcast2(a4.x); ffma2(acc[r][0], a, b[0].x); ffma2(acc[r][1], a, b[0].y);
            a = bcast2(a4.y); ffma2(acc[r][0], a, b[1].x); ffma2(acc[r][1], a, b[1].y);
            a = bcast2(a4.z); ffma2(acc[r][0], a, b[2].x); ffma2(acc[r][1], a, b[2].y);
            a = bcast2(a4.w); ffma2(acc[r][0], a, b[3].x); ffma2(acc[r][1], a, b[3].y);
        }
    }
}

// acc[8][4]: 8 rows x 8 cols, A-transpose: acc[e0+r][d0..] += sum_t A[t][e]*B[t][d].
__device__ __forceinline__ void gemmR(const float* __restrict__ A, int astr,
                                      const float* __restrict__ Bm, int bstr,
                                      int red, int e0, int d0,
                                      unsigned long long acc[8][4]) {
    #pragma unroll 4
    for (int t = 0; t < red; t++) {
        const float* br = Bm + t * bstr + d0;
        ulonglong2 b0 = *(const ulonglong2*)br;
        ulonglong2 b1 = *(const ulonglong2*)(br + 4);
        float4 alo = *(const float4*)(A + t * astr + e0);
        float4 ahi = *(const float4*)(A + t * astr + e0 + 4);
        float av[8] = {alo.x, alo.y, alo.z, alo.w, ahi.x, ahi.y, ahi.z, ahi.w};
        #pragma unroll
        for (int r = 0; r < 8; r++) {
            unsigned long long a = bcast2(av[r]);
            ffma2(acc[r][0], a, b0.x); ffma2(acc[r][1], a, b0.y);
            ffma2(acc[r][2], a, b1.x); ffma2(acc[r][3], a, b1.y);
        }
    }
}

// ---------------- Pass 0: trig table --------------------------------------------------
__global__ void __launch_bounds__(256, 1)
trig_kernel() {
    int idx = blockIdx.x * 256 + threadIdx.x;
    int t = idx >> 6, j = idx & 63;
    float invf = (float)exp(-((double)(2 * j) / 128.0) * log(10000.0));
    float sn, cs; sincos_safe((float)t * invf, &sn, &cs);
    g_trig[idx] = make_float2(cs, sn);
}

// ---------------- Pass 1: S[e][d] = sum_t Kr[t][e] V[t][d], streamed ------------------
__global__ void __launch_bounds__(256, 2)
kv_kernel(const float* __restrict__ K, const float* __restrict__ V) {
    __shared__ float sK[32 * QSTR];
    __shared__ float sV[32 * QSTR];
    int tid = threadIdx.x;
    int b = blockIdx.y, c = blockIdx.x;

    const float* gK = K + ((size_t)b * SS + (size_t)c * CC) * DD;
    const float* gV = V + ((size_t)b * SS + (size_t)c * CC) * DD;

    int tx = tid & 15, ty = tid >> 4;
    int e0 = ty * 8, d0 = tx * 8;
    unsigned long long acc[8][4];
    #pragma unroll
    for (int r = 0; r < 8; r++)
        #pragma unroll
        for (int p = 0; p < 4; p++) acc[r][p] = 0ull;

    for (int kb = 0; kb < 4; kb++) {
        __syncthreads();                            // prior gemmR readers done
        load_rope_tile(sK, gK + kb * 32 * DD, 32, c * CC + kb * 32, tid);
        load_tile(sV, gV + kb * 32 * DD, 32, tid);
        __syncthreads();
        gemmR(sK, QSTR, sV, QSTR, 32, e0, d0, acc);
    }

    float* out = (float*)g_kv4 + ((size_t)(b * NC + c)) * DD * DD;
    #pragma unroll
    for (int r = 0; r < 8; r++) {
        U2 u0, u1, u2, u3;
        u0.u = acc[r][0]; u1.u = acc[r][1]; u2.u = acc[r][2]; u3.u = acc[r][3];
        *(float4*)(out + (e0 + r) * DD + d0)     = make_float4(u0.f.x, u0.f.y, u1.f.x, u1.f.y);
        *(float4*)(out + (e0 + r) * DD + d0 + 4) = make_float4(u2.f.x, u2.f.y, u3.f.x, u3.f.y);
    }
}

// ---------------- Pass 2: exclusive prefix over chunk states --------------------------
__global__ void __launch_bounds__(256, 1)
prefix_kernel() {
    int b = blockIdx.y;
    int idx4 = blockIdx.x * 256 + threadIdx.x;
    const float4* kv = g_kv4  + (size_t)b * NC * 4096;
    float4*       pr = g_pre4 + (size_t)b * NC * 4096;
    float4 acc = make_float4(0.f, 0.f, 0.f, 0.f);
    #pragma unroll 8
    for (int c = 0; c < NC; c++) {
        pr[(size_t)c * 4096 + idx4] = acc;
        float4 v = kv[(size_t)c * 4096 + idx4];
        acc.x += v.x; acc.y += v.y; acc.z += v.z; acc.w += v.w;
    }
}

// ---------------- Pass 3: 64-row Q tiles ----------------------------------------------
__global__ void __launch_bounds__(256, 2)
out_kernel(const float* __restrict__ Q, const float* __restrict__ K,
           const float* __restrict__ V, float* __restrict__ O) {
    extern __shared__ float sm[];
    float* sQ = sm;                       // [64][QSTR]  33.8KB
    float* sK = sQ + 64 * QSTR;           // [32][QSTR]  (reused as sM in stage A)
    float* sV = sK + 32 * QSTR;           // [32][QSTR]
    float* sE = sV + 32 * QSTR;           // [64][ESTR]
    int tid = threadIdx.x;
    int b = blockIdx.y;
    int c = blockIdx.x >> 1, h = blockIdx.x & 1;
    int q0 = c * CC + h * 64;             // first global Q row of this tile

    load_rope_tile(sQ, Q + ((size_t)b * SS + q0) * DD, 64, q0, tid);
    // sQ ordered by the first barrier on either path below.

    int tx = tid & 31, ty = tid >> 5;     // out tile: 8 rows x 4 cols per thread
    int i0 = ty * 8, d0 = tx * 4;
    unsigned long long acc[8][2];
    #pragma unroll
    for (int r = 0; r < 8; r++) { acc[r][0] = 0ull; acc[r][1] = 0ull; }

    // Stage A: acc += Qr_tile @ M_prefix (M streamed 32 rows at a time into sK buf).
    if (c > 0) {
        const float* gM = (const float*)g_pre4 + ((size_t)(b * NC + c)) * DD * DD;
        for (int mb = 0; mb < 4; mb++) {
            __syncthreads();                        // orders sQ on mb==0; prior gemm readers
            load_tile(sK, gM + mb * 32 * DD, 32, tid);
            __syncthreads();
            gemmC4(sQ + mb * 32, QSTR, sK, QSTR, 32, i0, d0, acc);
        }
    }

    // Stage B: intra-chunk causal attention. h=0 tiles need K blocks 0..1, h=1 need 0..3.
    int tx4 = tid & 3, iy = tid >> 2;     // E tile: 1 row x 8 keys per thread
    const float* gKc = K + ((size_t)b * SS + (size_t)c * CC) * DD;
    const float* gVc = V + ((size_t)b * SS + (size_t)c * CC) * DD;
    int jmax = 2 + 2 * h;

    for (int j = 0; j < jmax; j++) {
        int j32 = j * 32;
        __syncthreads();                            // prior sK/sV/sE consumers done (or sQ)
        load_rope_tile(sK, gKc + j * 32 * DD, 32, c * CC + j32, tid);
        load_tile(sV, gVc + j * 32 * DD, 32, tid);
        __syncthreads();

        int g = h * 64 + iy;                        // chunk-local Q row of this thread
        if (g >= j32) {                             // warp-uniform (rows 8w..8w+7 vs 32-mult)
            unsigned long long eacc[8];
            #pragma unroll
            for (int u = 0; u < 8; u++) eacc[u] = 0ull;
            #pragma unroll 4
            for (int d4 = 0; d4 < 32; d4++) {
                ulonglong2 q2 = *(const ulonglong2*)(sQ + iy * QSTR + d4 * 4);
                #pragma unroll
                for (int u = 0; u < 8; u++) {
                    ulonglong2 k2 = *(const ulonglong2*)(sK + (u * 4 + tx4) * QSTR + d4 * 4);
                    ffma2(eacc[u], q2.x, k2.x); ffma2(eacc[u], q2.y, k2.y);
                }
            }
            #pragma unroll
            for (int u = 0; u < 8; u++) {
                int t = u * 4 + tx4;
                U2 v; v.u = eacc[u];
                float e = v.f.x + v.f.y;
                sE[iy * ESTR + t] = (j32 + t <= g) ? e : 0.0f;   // causal mask
            }
        }
        __syncthreads();
        if (h * 64 + i0 >= j32)                     // warp-uniform (i0 const per warp)
            gemmC4(sE, ESTR, sV, QSTR, 32, i0, d0, acc);
    }

    float* gO = O + ((size_t)b * SS + q0) * DD;
    #pragma unroll
    for (int r = 0; r < 8; r++) {
        U2 u0, u1; u0.u = acc[r][0]; u1.u = acc[r][1];
        *(float4*)(gO + (i0 + r) * DD + d0) = make_float4(u0.f.x, u0.f.y, u1.f.x, u1.f.y);
    }
}

extern "C" void kernel_launch(void* const* d_in, const int* in_sizes, int n_in,
                              void* d_out, int out_size) {
    const float* Q = (const float*)d_in[0];
    const float* K = (const float*)d_in[1];
    const float* V = (const float*)d_in[2];
    float* O = (float*)d_out;

    int smem3 = (64 * QSTR + 2 * 32 * QSTR + 64 * ESTR) * (int)sizeof(float);  // 76.8KB
    cudaFuncSetAttribute(out_kernel, cudaFuncAttributeMaxDynamicSharedMemorySize, smem3);

    trig_kernel<<<SS * 64 / 256, 256>>>();
    kv_kernel<<<dim3(NC, BB), 256>>>(K, V);
    prefix_kernel<<<dim3(16, BB), 256>>>();
    out_kernel<<<dim3(NC * 2, BB), 256, smem3>>>(Q, K, V, O);
}

// round 8
// speedup vs baseline: 1.5898x; 1.5898x over previous
#include <cuda_runtime.h>
#include <math.h>

// LinearAttention: out = tril(rope(Q) @ rope(K)^T) @ V
//   pass0: trig table; pass1: chunk KV states; pass2: exclusive prefix;
//   pass3: out = masked(Qr Kr^T) V + Qr @ M_prefix   (64-row tiles, 128 thr, 8x8)
// R6: out_kernel 8x8 thread tiles @ 3 CTAs/SM (swizzled sQ); kv reverted to
//     full-tile single-gemm (R3 form) + fused-rope load.
// R7: resubmission of R6 (broker outage) after full correctness re-audit.

#define BB 8
#define SS 4096
#define DD 128
#define CC 128
#define NC 32
#define QSTR 132       // padded stride for sK/sV (floats)
#define ESTR 36        // sE stride

__device__ float4 g_kv4 [(size_t)BB * NC * DD * DD / 4];
__device__ float4 g_pre4[(size_t)BB * NC * DD * DD / 4];
__device__ float2 g_trig[(size_t)SS * 64];

union U2 { unsigned long long u; float2 f; };

__device__ __forceinline__ void ffma2(unsigned long long &d,
                                      unsigned long long a,
                                      unsigned long long b) {
    asm("fma.rn.f32x2 %0, %1, %2, %0;" : "+l"(d) : "l"(a), "l"(b));
}
__device__ __forceinline__ unsigned long long bcast2(float x) {
    U2 u; u.f = make_float2(x, x); return u.u;
}
__device__ __forceinline__ int swg(int row, int g) { return g ^ (row & 7); }  // 16B-granule swizzle

// Plain copy into padded-stride smem.
template<int NT>
__device__ __forceinline__ void load_tile(float* sdst, const float* __restrict__ gsrc,
                                          int nrows, int tid) {
    int total = nrows * 32;
    for (int g = tid; g < total; g += NT) {
        int row = g >> 5, c4 = g & 31;
        *(float4*)(sdst + row * QSTR + c4 * 4) = ((const float4*)gsrc)[g];
    }
}

// Fused load+RoPE into padded-stride smem (sK in both kernels).
template<int NT>
__device__ __forceinline__ void load_rope_tile(float* sdst, const float* __restrict__ gsrc,
                                               int nrows, int srow0, int tid) {
    int total = nrows * 16;
    for (int g = tid; g < total; g += NT) {
        int row = g >> 4, c4 = g & 15;
        float4 a = ((const float4*)gsrc)[row * 32 + c4];
        float4 b = ((const float4*)gsrc)[row * 32 + c4 + 16];
        const float4* tp = (const float4*)(g_trig + (size_t)(srow0 + row) * 64 + c4 * 4);
        float4 t0 = tp[0], t1 = tp[1];
        float4 lo, hi;
        lo.x = a.x * t0.x - b.x * t0.y;  hi.x = b.x * t0.x + a.x * t0.y;
        lo.y = a.y * t0.z - b.y * t0.w;  hi.y = b.y * t0.z + a.y * t0.w;
        lo.z = a.z * t1.x - b.z * t1.y;  hi.z = b.z * t1.x + a.z * t1.y;
        lo.w = a.w * t1.z - b.w * t1.w;  hi.w = b.w * t1.z + a.w * t1.w;
        *(float4*)(sdst + row * QSTR + c4 * 4)      = lo;
        *(float4*)(sdst + row * QSTR + c4 * 4 + 64) = hi;
    }
}

// Fused load+RoPE into SWIZZLED stride-128 smem (sQ in out_kernel).
template<int NT>
__device__ __forceinline__ void load_rope_sw(float* sdst, const float* __restrict__ gsrc,
                                             int nrows, int srow0, int tid) {
    int total = nrows * 16;
    for (int g = tid; g < total; g += NT) {
        int row = g >> 4, c4 = g & 15;
        float4 a = ((const float4*)gsrc)[row * 32 + c4];
        float4 b = ((const float4*)gsrc)[row * 32 + c4 + 16];
        const float4* tp = (const float4*)(g_trig + (size_t)(srow0 + row) * 64 + c4 * 4);
        float4 t0 = tp[0], t1 = tp[1];
        float4 lo, hi;
        lo.x = a.x * t0.x - b.x * t0.y;  hi.x = b.x * t0.x + a.x * t0.y;
        lo.y = a.y * t0.z - b.y * t0.w;  hi.y = b.y * t0.z + a.y * t0.w;
        lo.z = a.z * t1.x - b.z * t1.y;  hi.z = b.z * t1.x + a.z * t1.y;
        lo.w = a.w * t1.z - b.w * t1.w;  hi.w = b.w * t1.z + a.w * t1.w;
        int gs = swg(row, c4);                       // (c4+16)^x = gs+16 for x<8
        *(float4*)(sdst + row * 128 + gs * 4)        = lo;
        *(float4*)(sdst + row * 128 + (gs + 16) * 4) = hi;
    }
}

__device__ __forceinline__ void sincos_safe(float ang, float* sn, float* cs) {
    float k = rintf(ang * 0.15915494309189535f);
    float r = fmaf(-k, 6.28125f, ang);
    r = fmaf(-k, 1.9353071795864769e-3f, r);
    sincosf(r, sn, cs);
}

// 8x8 gemm, A plain stride: acc[i0+r][d0..d0+7] += sum_e A[i][e]*B[e][d].
__device__ __forceinline__ void gemmC8(const float* __restrict__ A, int astr,
                                       const float* __restrict__ Bm, int bstr,
                                       int red, int i0, int d0,
                                       unsigned long long acc[8][4]) {
    #pragma unroll 2
    for (int e = 0; e < red; e += 4) {
        ulonglong2 b[4][2];
        #pragma unroll
        for (int k = 0; k < 4; k++) {
            const float* br = Bm + (e + k) * bstr + d0;
            b[k][0] = *(const ulonglong2*)br;
            b[k][1] = *(const ulonglong2*)(br + 4);
        }
        #pragma unroll
        for (int r = 0; r < 8; r++) {
            float4 a4 = *(const float4*)(A + (i0 + r) * astr + e);
            unsigned long long a;
            a = bcast2(a4.x);
            ffma2(acc[r][0], a, b[0][0].x); ffma2(acc[r][1], a, b[0][0].y);
            ffma2(acc[r][2], a, b[0][1].x); ffma2(acc[r][3], a, b[0][1].y);
            a = bcast2(a4.y);
            ffma2(acc[r][0], a, b[1][0].x); ffma2(acc[r][1], a, b[1][0].y);
            ffma2(acc[r][2], a, b[1][1].x); ffma2(acc[r][3], a, b[1][1].y);
            a = bcast2(a4.z);
            ffma2(acc[r][0], a, b[2][0].x); ffma2(acc[r][1], a, b[2][0].y);
            ffma2(acc[r][2], a, b[2][1].x); ffma2(acc[r][3], a, b[2][1].y);
            a = bcast2(a4.w);
            ffma2(acc[r][0], a, b[3][0].x); ffma2(acc[r][1], a, b[3][0].y);
            ffma2(acc[r][2], a, b[3][1].x); ffma2(acc[r][3], a, b[3][1].y);
        }
    }
}

// 8x8 gemm, A = swizzled stride-128 sQ, reduction columns ecol0..ecol0+31.
__device__ __forceinline__ void gemmC8_sw(const float* __restrict__ Aq, int ecol0,
                                          const float* __restrict__ Bm, int bstr,
                                          int i0, int d0,
                                          unsigned long long acc[8][4]) {
    #pragma unroll 2
    for (int e = 0; e < 32; e += 4) {
        ulonglong2 b[4][2];
        #pragma unroll
        for (int k = 0; k < 4; k++) {
            const float* br = Bm + (e + k) * bstr + d0;
            b[k][0] = *(const ulonglong2*)br;
            b[k][1] = *(const ulonglong2*)(br + 4);
        }
        int gcol = (ecol0 + e) >> 2;
        #pragma unroll
        for (int r = 0; r < 8; r++) {
            int arow = i0 + r;
            float4 a4 = *(const float4*)(Aq + arow * 128 + swg(arow, gcol) * 4);
            unsigned long long a;
            a = bcast2(a4.x);
            ffma2(acc[r][0], a, b[0][0].x); ffma2(acc[r][1], a, b[0][0].y);
            ffma2(acc[r][2], a, b[0][1].x); ffma2(acc[r][3], a, b[0][1].y);
            a = bcast2(a4.y);
            ffma2(acc[r][0], a, b[1][0].x); ffma2(acc[r][1], a, b[1][0].y);
            ffma2(acc[r][2], a, b[1][1].x); ffma2(acc[r][3], a, b[1][1].y);
            a = bcast2(a4.z);
            ffma2(acc[r][0], a, b[2][0].x); ffma2(acc[r][1], a, b[2][0].y);
            ffma2(acc[r][2], a, b[2][1].x); ffma2(acc[r][3], a, b[2][1].y);
            a = bcast2(a4.w);
            ffma2(acc[r][0], a, b[3][0].x); ffma2(acc[r][1], a, b[3][0].y);
            ffma2(acc[r][2], a, b[3][1].x); ffma2(acc[r][3], a, b[3][1].y);
        }
    }
}

// A-transpose 8x8: acc[e0+r][d0..] += sum_t A[t][e]*B[t][d]  (both padded QSTR).
__device__ __forceinline__ void gemmR(const float* __restrict__ A, int astr,
                                      const float* __restrict__ Bm, int bstr,
                                      int red, int e0, int d0,
                                      unsigned long long acc[8][4]) {
    #pragma unroll 4
    for (int t = 0; t < red; t++) {
        const float* br = Bm + t * bstr + d0;
        ulonglong2 b0 = *(const ulonglong2*)br;
        ulonglong2 b1 = *(const ulonglong2*)(br + 4);
        float4 alo = *(const float4*)(A + t * astr + e0);
        float4 ahi = *(const float4*)(A + t * astr + e0 + 4);
        float av[8] = {alo.x, alo.y, alo.z, alo.w, ahi.x, ahi.y, ahi.z, ahi.w};
        #pragma unroll
        for (int r = 0; r < 8; r++) {
            unsigned long long a = bcast2(av[r]);
            ffma2(acc[r][0], a, b0.x); ffma2(acc[r][1], a, b0.y);
            ffma2(acc[r][2], a, b1.x); ffma2(acc[r][3], a, b1.y);
        }
    }
}

__device__ __forceinline__ void store_acc8x8(float* dst, int dstr, int i0, int d0,
                                             unsigned long long acc[8][4]) {
    #pragma unroll
    for (int r = 0; r < 8; r++) {
        U2 u0, u1, u2, u3;
        u0.u = acc[r][0]; u1.u = acc[r][1]; u2.u = acc[r][2]; u3.u = acc[r][3];
        *(float4*)(dst + (i0 + r) * dstr + d0)     = make_float4(u0.f.x, u0.f.y, u1.f.x, u1.f.y);
        *(float4*)(dst + (i0 + r) * dstr + d0 + 4) = make_float4(u2.f.x, u2.f.y, u3.f.x, u3.f.y);
    }
}

// ---------------- Pass 0: trig table --------------------------------------------------
__global__ void __launch_bounds__(256, 1)
trig_kernel() {
    int idx = blockIdx.x * 256 + threadIdx.x;
    int t = idx >> 6, j = idx & 63;
    float invf = (float)exp(-((double)(2 * j) / 128.0) * log(10000.0));
    float sn, cs; sincos_safe((float)t * invf, &sn, &cs);
    g_trig[idx] = make_float2(cs, sn);
}

// ---------------- Pass 1: full-tile chunk state (R3 form + fused rope) ----------------
__global__ void __launch_bounds__(256, 1)
kv_kernel(const float* __restrict__ K, const float* __restrict__ V) {
    extern __shared__ float sm[];
    float* sK = sm;                       // [128][QSTR]
    float* sV = sm + 128 * QSTR;          // [128][QSTR]
    int tid = threadIdx.x;
    int b = blockIdx.y, c = blockIdx.x;

    const float* gK = K + ((size_t)b * SS + (size_t)c * CC) * DD;
    const float* gV = V + ((size_t)b * SS + (size_t)c * CC) * DD;
    load_rope_tile<256>(sK, gK, 128, c * CC, tid);
    load_tile<256>(sV, gV, 128, tid);
    __syncthreads();

    int tx = tid & 15, ty = tid >> 4;
    int e0 = ty * 8, d0 = tx * 8;
    unsigned long long acc[8][4];
    #pragma unroll
    for (int r = 0; r < 8; r++)
        #pragma unroll
        for (int p = 0; p < 4; p++) acc[r][p] = 0ull;

    gemmR(sK, QSTR, sV, QSTR, 128, e0, d0, acc);

    float* out = (float*)g_kv4 + ((size_t)(b * NC + c)) * DD * DD;
    store_acc8x8(out, DD, e0, d0, acc);
}

// ---------------- Pass 2: exclusive prefix --------------------------------------------
__global__ void __launch_bounds__(256, 1)
prefix_kernel() {
    int b = blockIdx.y;
    int idx4 = blockIdx.x * 256 + threadIdx.x;
    const float4* kv = g_kv4  + (size_t)b * NC * 4096;
    float4*       pr = g_pre4 + (size_t)b * NC * 4096;
    float4 acc = make_float4(0.f, 0.f, 0.f, 0.f);
    #pragma unroll 8
    for (int c = 0; c < NC; c++) {
        pr[(size_t)c * 4096 + idx4] = acc;
        float4 v = kv[(size_t)c * 4096 + idx4];
        acc.x += v.x; acc.y += v.y; acc.z += v.z; acc.w += v.w;
    }
}

// ---------------- Pass 3: 64-row tiles, 128 threads, 8x8, 3 CTAs/SM -------------------
__global__ void __launch_bounds__(128, 3)
out_kernel(const float* __restrict__ Q, const float* __restrict__ K,
           const float* __restrict__ V, float* __restrict__ O) {
    extern __shared__ float sm[];
    float* sQ = sm;                       // [64][128] swizzled, 32768 B
    float* sK = sQ + 64 * 128;            // [32][QSTR] 16896 B (reused as sM)
    float* sV = sK + 32 * QSTR;           // [32][QSTR] 16896 B
    float* sE = sV + 32 * QSTR;           // [64][ESTR]  9216 B   (total 75776 B)
    int tid = threadIdx.x;
    int b = blockIdx.y;
    int c = blockIdx.x >> 1, h = blockIdx.x & 1;
    int q0 = c * CC + h * 64;

    load_rope_sw<128>(sQ, Q + ((size_t)b * SS + q0) * DD, 64, q0, tid);
    // sQ ordered by the first barrier on either path below.

    int tx = tid & 15, ty = tid >> 4;     // 8 rows x 8 cols per thread
    int i0 = ty * 8, d0 = tx * 8;
    unsigned long long acc[8][4];
    #pragma unroll
    for (int r = 0; r < 8; r++)
        #pragma unroll
        for (int p = 0; p < 4; p++) acc[r][p] = 0ull;

    // Stage A: acc += Qr_tile @ M_prefix (M streamed into sK buffer).
    if (c > 0) {
        const float* gM = (const float*)g_pre4 + ((size_t)(b * NC + c)) * DD * DD;
        for (int mb = 0; mb < 4; mb++) {
            __syncthreads();
            load_tile<128>(sK, gM + mb * 32 * DD, 32, tid);
            __syncthreads();
            gemmC8_sw(sQ, mb * 32, sK, QSTR, i0, d0, acc);
        }
    }

    // Stage B: intra-chunk causal attention.
    int tx4 = tid & 3, iy = tid >> 2;     // E: 2 rows x 8 keys per thread
    int r0 = iy * 2;
    const float* gKc = K + ((size_t)b * SS + (size_t)c * CC) * DD;
    const float* gVc = V + ((size_t)b * SS + (size_t)c * CC) * DD;
    int jmax = 2 + 2 * h;

    for (int j = 0; j < jmax; j++) {
        int j32 = j * 32;
        __syncthreads();
        load_rope_tile<128>(sK, gKc + j * 32 * DD, 32, c * CC + j32, tid);
        load_tile<128>(sV, gVc + j * 32 * DD, 32, tid);
        __syncthreads();

        if (h * 64 + r0 >= j32) {                    // warp-uniform
            unsigned long long eacc[2][8];
            #pragma unroll
            for (int r = 0; r < 2; r++)
                #pragma unroll
                for (int u = 0; u < 8; u++) eacc[r][u] = 0ull;
            #pragma unroll 4
            for (int d4 = 0; d4 < 32; d4++) {
                ulonglong2 q0v = *(const ulonglong2*)(sQ + r0 * 128 + swg(r0, d4) * 4);
                ulonglong2 q1v = *(const ulonglong2*)(sQ + (r0 + 1) * 128 + swg(r0 + 1, d4) * 4);
                #pragma unroll
                for (int u = 0; u < 8; u++) {
                    ulonglong2 k2 = *(const ulonglong2*)(sK + (u * 4 + tx4) * QSTR + d4 * 4);
                    ffma2(eacc[0][u], q0v.x, k2.x); ffma2(eacc[0][u], q0v.y, k2.y);
                    ffma2(eacc[1][u], q1v.x, k2.x); ffma2(eacc[1][u], q1v.y, k2.y);
                }
            }
            #pragma unroll
            for (int r = 0; r < 2; r++) {
                int i = r0 + r, gi = h * 64 + i;
                #pragma unroll
                for (int u = 0; u < 8; u++) {
                    int t = u * 4 + tx4;
                    U2 v; v.u = eacc[r][u];
                    float e = v.f.x + v.f.y;
                    sE[i * ESTR + t] = (j32 + t <= gi) ? e : 0.0f;
                }
            }
        }
        __syncthreads();
        if (h * 64 + i0 >= j32)                      // warp-uniform
            gemmC8(sE, ESTR, sV, QSTR, 32, i0, d0, acc);
    }

    float* gO = O + ((size_t)b * SS + q0) * DD;
    store_acc8x8(gO, DD, i0, d0, acc);
}

extern "C" void kernel_launch(void* const* d_in, const int* in_sizes, int n_in,
                              void* d_out, int out_size) {
    const float* Q = (const float*)d_in[0];
    const float* K = (const float*)d_in[1];
    const float* V = (const float*)d_in[2];
    float* O = (float*)d_out;

    int smem1 = 2 * 128 * QSTR * (int)sizeof(float);                 // 135168
    int smem3 = (64 * 128 + 2 * 32 * QSTR + 64 * ESTR) * (int)sizeof(float);  // 75776
    cudaFuncSetAttribute(kv_kernel,  cudaFuncAttributeMaxDynamicSharedMemorySize, smem1);
    cudaFuncSetAttribute(out_kernel, cudaFuncAttributeMaxDynamicSharedMemorySize, smem3);

    trig_kernel<<<SS * 64 / 256, 256>>>();
    kv_kernel<<<dim3(NC, BB), 256, smem1>>>(K, V);
    prefix_kernel<<<dim3(16, BB), 256>>>();
    out_kernel<<<dim3(NC * 2, BB), 128, smem3>>>(Q, K, V, O);
}

// round 9
// speedup vs baseline: 1.6230x; 1.0209x over previous
#include <cuda_runtime.h>
#include <math.h>

// LinearAttention: out = tril(rope(Q) @ rope(K)^T) @ V
//   pass0: trig table; pass1: chunk KV states (also emits pre-roped K -> g_kr);
//   pass2: exclusive prefix; pass3: pipelined out kernel (cp.async double buffer).
// R8: out_kernel software pipeline — all tile loads are cp.async pure copies
//     (K pre-roped by pass1), double-buffered, 1 bar per stage-A iter.

#define BB 8
#define SS 4096
#define DD 128
#define CC 128
#define NC 32
#define QSTR 132       // padded stride for K/V/M smem tiles (floats)
#define ESTR 36        // sE stride

__device__ float4 g_kv4 [(size_t)BB * NC * DD * DD / 4];
__device__ float4 g_pre4[(size_t)BB * NC * DD * DD / 4];
__device__ float2 g_trig[(size_t)SS * 64];
__device__ float  g_kr  [(size_t)BB * SS * DD];       // 16MB pre-roped K

union U2 { unsigned long long u; float2 f; };

__device__ __forceinline__ void ffma2(unsigned long long &d,
                                      unsigned long long a,
                                      unsigned long long b) {
    asm("fma.rn.f32x2 %0, %1, %2, %0;" : "+l"(d) : "l"(a), "l"(b));
}
__device__ __forceinline__ unsigned long long bcast2(float x) {
    U2 u; u.f = make_float2(x, x); return u.u;
}
__device__ __forceinline__ int swg(int row, int g) { return g ^ (row & 7); }

__device__ __forceinline__ void cpa16(float* sdst, const float* gsrc) {
    unsigned sa = (unsigned)__cvta_generic_to_shared(sdst);
    asm volatile("cp.async.cg.shared.global [%0], [%1], 16;" :: "r"(sa), "l"(gsrc));
}
__device__ __forceinline__ void cpa_commit() {
    asm volatile("cp.async.commit_group;" ::: "memory");
}
__device__ __forceinline__ void cpa_wait_all() {
    asm volatile("cp.async.wait_group 0;" ::: "memory");
}

// Async copy of a 32x128 float tile into padded smem.
template<int NT>
__device__ __forceinline__ void issue_tile(float* sdst, const float* __restrict__ gsrc,
                                           int tid) {
    #pragma unroll
    for (int g = tid; g < 1024; g += NT) {
        int row = g >> 5, c4 = g & 31;
        cpa16(sdst + row * QSTR + c4 * 4, gsrc + row * 128 + c4 * 4);
    }
}

// Plain copy into padded-stride smem.
template<int NT>
__device__ __forceinline__ void load_tile(float* sdst, const float* __restrict__ gsrc,
                                          int nrows, int tid) {
    int total = nrows * 32;
    for (int g = tid; g < total; g += NT) {
        int row = g >> 5, c4 = g & 31;
        *(float4*)(sdst + row * QSTR + c4 * 4) = ((const float4*)gsrc)[g];
    }
}

// Fused load+RoPE into padded smem AND pre-roped copy to gmem (kv_kernel).
template<int NT>
__device__ __forceinline__ void load_rope_store(float* sdst, float* __restrict__ gdst,
                                                const float* __restrict__ gsrc,
                                                int nrows, int srow0, int tid) {
    int total = nrows * 16;
    for (int g = tid; g < total; g += NT) {
        int row = g >> 4, c4 = g & 15;
        float4 a = ((const float4*)gsrc)[row * 32 + c4];
        float4 b = ((const float4*)gsrc)[row * 32 + c4 + 16];
        const float4* tp = (const float4*)(g_trig + (size_t)(srow0 + row) * 64 + c4 * 4);
        float4 t0 = tp[0], t1 = tp[1];
        float4 lo, hi;
        lo.x = a.x * t0.x - b.x * t0.y;  hi.x = b.x * t0.x + a.x * t0.y;
        lo.y = a.y * t0.z - b.y * t0.w;  hi.y = b.y * t0.z + a.y * t0.w;
        lo.z = a.z * t1.x - b.z * t1.y;  hi.z = b.z * t1.x + a.z * t1.y;
        lo.w = a.w * t1.z - b.w * t1.w;  hi.w = b.w * t1.z + a.w * t1.w;
        *(float4*)(sdst + row * QSTR + c4 * 4)      = lo;
        *(float4*)(sdst + row * QSTR + c4 * 4 + 64) = hi;
        *(float4*)(gdst + row * 128 + c4 * 4)       = lo;
        *(float4*)(gdst + row * 128 + c4 * 4 + 64)  = hi;
    }
}

// Fused load+RoPE into SWIZZLED stride-128 smem (sQ in out_kernel).
template<int NT>
__device__ __forceinline__ void load_rope_sw(float* sdst, const float* __restrict__ gsrc,
                                             int nrows, int srow0, int tid) {
    int total = nrows * 16;
    for (int g = tid; g < total; g += NT) {
        int row = g >> 4, c4 = g & 15;
        float4 a = ((const float4*)gsrc)[row * 32 + c4];
        float4 b = ((const float4*)gsrc)[row * 32 + c4 + 16];
        const float4* tp = (const float4*)(g_trig + (size_t)(srow0 + row) * 64 + c4 * 4);
        float4 t0 = tp[0], t1 = tp[1];
        float4 lo, hi;
        lo.x = a.x * t0.x - b.x * t0.y;  hi.x = b.x * t0.x + a.x * t0.y;
        lo.y = a.y * t0.z - b.y * t0.w;  hi.y = b.y * t0.z + a.y * t0.w;
        lo.z = a.z * t1.x - b.z * t1.y;  hi.z = b.z * t1.x + a.z * t1.y;
        lo.w = a.w * t1.z - b.w * t1.w;  hi.w = b.w * t1.z + a.w * t1.w;
        int gs = swg(row, c4);
        *(float4*)(sdst + row * 128 + gs * 4)        = lo;
        *(float4*)(sdst + row * 128 + (gs + 16) * 4) = hi;
    }
}

__device__ __forceinline__ void sincos_safe(float ang, float* sn, float* cs) {
    float k = rintf(ang * 0.15915494309189535f);
    float r = fmaf(-k, 6.28125f, ang);
    r = fmaf(-k, 1.9353071795864769e-3f, r);
    sincosf(r, sn, cs);
}

// 8x8 gemm, A plain stride: acc[i0+r][d0..d0+7] += sum_e A[i][e]*B[e][d].
__device__ __forceinline__ void gemmC8(const float* __restrict__ A, int astr,
                                       const float* __restrict__ Bm, int bstr,
                                       int red, int i0, int d0,
                                       unsigned long long acc[8][4]) {
    #pragma unroll 2
    for (int e = 0; e < red; e += 4) {
        ulonglong2 b[4][2];
        #pragma unroll
        for (int k = 0; k < 4; k++) {
            const float* br = Bm + (e + k) * bstr + d0;
            b[k][0] = *(const ulonglong2*)br;
            b[k][1] = *(const ulonglong2*)(br + 4);
        }
        #pragma unroll
        for (int r = 0; r < 8; r++) {
            float4 a4 = *(const float4*)(A + (i0 + r) * astr + e);
            unsigned long long a;
            a = bcast2(a4.x);
            ffma2(acc[r][0], a, b[0][0].x); ffma2(acc[r][1], a, b[0][0].y);
            ffma2(acc[r][2], a, b[0][1].x); ffma2(acc[r][3], a, b[0][1].y);
            a = bcast2(a4.y);
            ffma2(acc[r][0], a, b[1][0].x); ffma2(acc[r][1], a, b[1][0].y);
            ffma2(acc[r][2], a, b[1][1].x); ffma2(acc[r][3], a, b[1][1].y);
            a = bcast2(a4.z);
            ffma2(acc[r][0], a, b[2][0].x); ffma2(acc[r][1], a, b[2][0].y);
            ffma2(acc[r][2], a, b[2][1].x); ffma2(acc[r][3], a, b[2][1].y);
            a = bcast2(a4.w);
            ffma2(acc[r][0], a, b[3][0].x); ffma2(acc[r][1], a, b[3][0].y);
            ffma2(acc[r][2], a, b[3][1].x); ffma2(acc[r][3], a, b[3][1].y);
        }
    }
}

// 8x8 gemm, A = swizzled stride-128 sQ, reduction columns ecol0..ecol0+31.
__device__ __forceinline__ void gemmC8_sw(const float* __restrict__ Aq, int ecol0,
                                          const float* __restrict__ Bm, int bstr,
                                          int i0, int d0,
                                          unsigned long long acc[8][4]) {
    #pragma unroll 2
    for (int e = 0; e < 32; e += 4) {
        ulonglong2 b[4][2];
        #pragma unroll
        for (int k = 0; k < 4; k++) {
            const float* br = Bm + (e + k) * bstr + d0;
            b[k][0] = *(const ulonglong2*)br;
            b[k][1] = *(const ulonglong2*)(br + 4);
        }
        int gcol = (ecol0 + e) >> 2;
        #pragma unroll
        for (int r = 0; r < 8; r++) {
            int arow = i0 + r;
            float4 a4 = *(const float4*)(Aq + arow * 128 + swg(arow, gcol) * 4);
            unsigned long long a;
            a = bcast2(a4.x);
            ffma2(acc[r][0], a, b[0][0].x); ffma2(acc[r][1], a, b[0][0].y);
            ffma2(acc[r][2], a, b[0][1].x); ffma2(acc[r][3], a, b[0][1].y);
            a = bcast2(a4.y);
            ffma2(acc[r][0], a, b[1][0].x); ffma2(acc[r][1], a, b[1][0].y);
            ffma2(acc[r][2], a, b[1][1].x); ffma2(acc[r][3], a, b[1][1].y);
            a = bcast2(a4.z);
            ffma2(acc[r][0], a, b[2][0].x); ffma2(acc[r][1], a, b[2][0].y);
            ffma2(acc[r][2], a, b[2][1].x); ffma2(acc[r][3], a, b[2][1].y);
            a = bcast2(a4.w);
            ffma2(acc[r][0], a, b[3][0].x); ffma2(acc[r][1], a, b[3][0].y);
            ffma2(acc[r][2], a, b[3][1].x); ffma2(acc[r][3], a, b[3][1].y);
        }
    }
}

// A-transpose 8x8: acc[e0+r][d0..] += sum_t A[t][e]*B[t][d]  (both padded QSTR).
__device__ __forceinline__ void gemmR(const float* __restrict__ A, int astr,
                                      const float* __restrict__ Bm, int bstr,
                                      int red, int e0, int d0,
                                      unsigned long long acc[8][4]) {
    #pragma unroll 4
    for (int t = 0; t < red; t++) {
        const float* br = Bm + t * bstr + d0;
        ulonglong2 b0 = *(const ulonglong2*)br;
        ulonglong2 b1 = *(const ulonglong2*)(br + 4);
        float4 alo = *(const float4*)(A + t * astr + e0);
        float4 ahi = *(const float4*)(A + t * astr + e0 + 4);
        float av[8] = {alo.x, alo.y, alo.z, alo.w, ahi.x, ahi.y, ahi.z, ahi.w};
        #pragma unroll
        for (int r = 0; r < 8; r++) {
            unsigned long long a = bcast2(av[r]);
            ffma2(acc[r][0], a, b0.x); ffma2(acc[r][1], a, b0.y);
            ffma2(acc[r][2], a, b1.x); ffma2(acc[r][3], a, b1.y);
        }
    }
}

__device__ __forceinline__ void store_acc8x8(float* dst, int dstr, int i0, int d0,
                                             unsigned long long acc[8][4]) {
    #pragma unroll
    for (int r = 0; r < 8; r++) {
        U2 u0, u1, u2, u3;
        u0.u = acc[r][0]; u1.u = acc[r][1]; u2.u = acc[r][2]; u3.u = acc[r][3];
        *(float4*)(dst + (i0 + r) * dstr + d0)     = make_float4(u0.f.x, u0.f.y, u1.f.x, u1.f.y);
        *(float4*)(dst + (i0 + r) * dstr + d0 + 4) = make_float4(u2.f.x, u2.f.y, u3.f.x, u3.f.y);
    }
}

// ---------------- Pass 0: trig table --------------------------------------------------
__global__ void __launch_bounds__(256, 1)
trig_kernel() {
    int idx = blockIdx.x * 256 + threadIdx.x;
    int t = idx >> 6, j = idx & 63;
    float invf = (float)exp(-((double)(2 * j) / 128.0) * log(10000.0));
    float sn, cs; sincos_safe((float)t * invf, &sn, &cs);
    g_trig[idx] = make_float2(cs, sn);
}

// ---------------- Pass 1: chunk state + pre-roped K emission --------------------------
__global__ void __launch_bounds__(256, 1)
kv_kernel(const float* __restrict__ K, const float* __restrict__ V) {
    extern __shared__ float sm[];
    float* sK = sm;                       // [128][QSTR]
    float* sV = sm + 128 * QSTR;          // [128][QSTR]
    int tid = threadIdx.x;
    int b = blockIdx.y, c = blockIdx.x;

    const float* gK = K + ((size_t)b * SS + (size_t)c * CC) * DD;
    const float* gV = V + ((size_t)b * SS + (size_t)c * CC) * DD;
    float* gKr = g_kr + ((size_t)b * SS + (size_t)c * CC) * DD;
    load_rope_store<256>(sK, gKr, gK, 128, c * CC, tid);
    load_tile<256>(sV, gV, 128, tid);
    __syncthreads();

    int tx = tid & 15, ty = tid >> 4;
    int e0 = ty * 8, d0 = tx * 8;
    unsigned long long acc[8][4];
    #pragma unroll
    for (int r = 0; r < 8; r++)
        #pragma unroll
        for (int p = 0; p < 4; p++) acc[r][p] = 0ull;

    gemmR(sK, QSTR, sV, QSTR, 128, e0, d0, acc);

    float* out = (float*)g_kv4 + ((size_t)(b * NC + c)) * DD * DD;
    store_acc8x8(out, DD, e0, d0, acc);
}

// ---------------- Pass 2: exclusive prefix --------------------------------------------
__global__ void __launch_bounds__(256, 1)
prefix_kernel() {
    int b = blockIdx.y;
    int idx4 = blockIdx.x * 256 + threadIdx.x;
    const float4* kv = g_kv4  + (size_t)b * NC * 4096;
    float4*       pr = g_pre4 + (size_t)b * NC * 4096;
    float4 acc = make_float4(0.f, 0.f, 0.f, 0.f);
    #pragma unroll 8
    for (int c = 0; c < NC; c++) {
        pr[(size_t)c * 4096 + idx4] = acc;
        float4 v = kv[(size_t)c * 4096 + idx4];
        acc.x += v.x; acc.y += v.y; acc.z += v.z; acc.w += v.w;
    }
}

// ---------------- Pass 3: pipelined 64-row tiles, cp.async double buffer --------------
__global__ void __launch_bounds__(128, 2)
out_kernel(const float* __restrict__ Q, const float* __restrict__ V,
           float* __restrict__ O) {
    extern __shared__ float sm[];
    float* sQ  = sm;                      // [64][128] swizzled   32768 B
    float* kb0 = sQ + 64 * 128;           // [32][QSTR]           16896 B
    float* kb1 = kb0 + 32 * QSTR;
    float* vb0 = kb1 + 32 * QSTR;
    float* vb1 = vb0 + 32 * QSTR;
    float* sE  = vb1 + 32 * QSTR;         // [64][ESTR]            9216 B  (109568 total)
    float* kb[2] = {kb0, kb1};
    float* vb[2] = {vb0, vb1};
    int tid = threadIdx.x;
    int b = blockIdx.y;
    int c = blockIdx.x >> 1, h = blockIdx.x & 1;
    int q0 = c * CC + h * 64;

    int nA = (c > 0) ? 4 : 0;
    int jmax = 2 + 2 * h;
    int nTot = nA + jmax;
    const float* gM  = (const float*)g_pre4 + ((size_t)(b * NC + c)) * DD * DD;
    const float* gKr = g_kr + ((size_t)b * SS + (size_t)c * CC) * DD;
    const float* gV  = V + ((size_t)b * SS + (size_t)c * CC) * DD;

    // Issue the async loads for iteration `it` into buffer it&1 and commit.
    auto issue_it = [&](int it) {
        int s = it & 1;
        if (it < nA) {
            issue_tile<128>(kb[s], gM + it * 32 * DD, tid);
        } else {
            int j = it - nA;
            issue_tile<128>(kb[s], gKr + j * 32 * DD, tid);
            issue_tile<128>(vb[s], gV + j * 32 * DD, tid);
        }
        cpa_commit();
    };

    issue_it(0);                                    // start transfers first
    load_rope_sw<128>(sQ, Q + ((size_t)b * SS + q0) * DD, 64, q0, tid);

    int tx = tid & 15, ty = tid >> 4;
    int i0 = ty * 8, d0 = tx * 8;
    int tx4 = tid & 3, iy = tid >> 2;
    int r0 = iy * 2;
    unsigned long long acc[8][4];
    #pragma unroll
    for (int r = 0; r < 8; r++)
        #pragma unroll
        for (int p = 0; p < 4; p++) acc[r][p] = 0ull;

    for (int it = 0; it < nTot; it++) {
        cpa_wait_all();                             // data for `it` resident
        __syncthreads();                            // ...visible to all; old bufs free
        if (it + 1 < nTot) issue_it(it + 1);        // overlap next transfer with gemm
        int s = it & 1;

        if (it < nA) {
            gemmC8_sw(sQ, it * 32, kb[s], QSTR, i0, d0, acc);
        } else {
            int j = it - nA, j32 = j * 32;
            if (h * 64 + r0 >= j32) {               // warp-uniform triangular skip
                unsigned long long eacc[2][8];
                #pragma unroll
                for (int r = 0; r < 2; r++)
                    #pragma unroll
                    for (int u = 0; u < 8; u++) eacc[r][u] = 0ull;
                #pragma unroll 4
                for (int d4 = 0; d4 < 32; d4++) {
                    ulonglong2 q0v = *(const ulonglong2*)(sQ + r0 * 128 + swg(r0, d4) * 4);
                    ulonglong2 q1v = *(const ulonglong2*)(sQ + (r0 + 1) * 128 + swg(r0 + 1, d4) * 4);
                    #pragma unroll
                    for (int u = 0; u < 8; u++) {
                        ulonglong2 k2 = *(const ulonglong2*)(kb[s] + (u * 4 + tx4) * QSTR + d4 * 4);
                        ffma2(eacc[0][u], q0v.x, k2.x); ffma2(eacc[0][u], q0v.y, k2.y);
                        ffma2(eacc[1][u], q1v.x, k2.x); ffma2(eacc[1][u], q1v.y, k2.y);
                    }
                }
                #pragma unroll
                for (int r = 0; r < 2; r++) {
                    int i = r0 + r, gi = h * 64 + i;
                    #pragma unroll
                    for (int u = 0; u < 8; u++) {
                        int t = u * 4 + tx4;
                        U2 v; v.u = eacc[r][u];
                        float e = v.f.x + v.f.y;
                        sE[i * ESTR + t] = (j32 + t <= gi) ? e : 0.0f;
                    }
                }
            }
            __syncthreads();                        // sE produced -> consumed
            if (h * 64 + i0 >= j32)                 // warp-uniform
                gemmC8(sE, ESTR, vb[s], QSTR, 32, i0, d0, acc);
        }
    }

    float* gO = O + ((size_t)b * SS + q0) * DD;
    store_acc8x8(gO, DD, i0, d0, acc);
}

extern "C" void kernel_launch(void* const* d_in, const int* in_sizes, int n_in,
                              void* d_out, int out_size) {
    const float* Q = (const float*)d_in[0];
    const float* K = (const float*)d_in[1];
    const float* V = (const float*)d_in[2];
    float* O = (float*)d_out;

    int smem1 = 2 * 128 * QSTR * (int)sizeof(float);                              // 135168
    int smem3 = (64 * 128 + 4 * 32 * QSTR + 64 * ESTR) * (int)sizeof(float);      // 109568
    cudaFuncSetAttribute(kv_kernel,  cudaFuncAttributeMaxDynamicSharedMemorySize, smem1);
    cudaFuncSetAttribute(out_kernel, cudaFuncAttributeMaxDynamicSharedMemorySize, smem3);

    trig_kernel<<<SS * 64 / 256, 256>>>();
    kv_kernel<<<dim3(NC, BB), 256, smem1>>>(K, V);
    prefix_kernel<<<dim3(16, BB), 256>>>();
    out_kernel<<<dim3(NC * 2, BB), 128, smem3>>>(Q, V, O);
}